// round 17
// baseline (speedup 1.0000x reference)
#include <cuda_runtime.h>

#define B 512
#define T 512
#define H 128
#define G4 (4 * H)  // 512

typedef unsigned long long u64;

// g_P stores P = 2^{min(2*log2e*w1e, 15)} as [b][h/4][t'][perm(h%4)] quads,
// perm = {0,2,1,3} (pair-interleaved for f32x2 lanes)
__device__ float g_P[(size_t)B * H * T];

#define K2LOG2E 2.885390082f  // 2*log2(e)
#define ONE2 0x3F8000003F800000ULL

__device__ __forceinline__ float ex2f(float x) {
    float r;
    asm("ex2.approx.f32 %0, %1;" : "=f"(r) : "f"(x));
    return r;
}
__device__ __forceinline__ float rcpf(float x) {
    float r;
    asm("rcp.approx.f32 %0, %1;" : "=f"(r) : "f"(x));
    return r;
}
__device__ __forceinline__ float copysign_bits(float mag, float sgn) {
    unsigned int m = __float_as_uint(mag) & 0x7fffffffu;
    unsigned int s = __float_as_uint(sgn) & 0x80000000u;
    return __uint_as_float(m | s);
}
// ---- packed f32x2 (sm_100a) ----
__device__ __forceinline__ u64 fma2(u64 a, u64 b, u64 c) {
    u64 d;
    asm("fma.rn.f32x2 %0, %1, %2, %3;" : "=l"(d) : "l"(a), "l"(b), "l"(c));
    return d;
}
__device__ __forceinline__ u64 mul2(u64 a, u64 b) {
    u64 d;
    asm("mul.rn.f32x2 %0, %1, %2;" : "=l"(d) : "l"(a), "l"(b));
    return d;
}
__device__ __forceinline__ void unpack2(u64 v, float& lo, float& hi) {
    asm("mov.b64 {%0, %1}, %2;" : "=f"(lo), "=f"(hi) : "l"(v));
}

// ---- gate tanh: negative-exponent safe form + Newton (accurate, NaN-proof) ----
__device__ __forceinline__ float tanh_safe(float x) {
    float y = x * K2LOG2E;
    float m = fminf(y, -y);         // -|y|
    float E = ex2f(m);              // e^{-2|x|} in (0,1]
    float den = E + 1.0f;
    float r = rcpf(den);
    r = r * fmaf(-den, r, 2.0f);    // Newton (den in [1,2], safe)
    float t = (1.0f - E) * r;
    return copysign_bits(t, x);
}

// perm slot for h-index j within its quad: {0,2,1,3}
__device__ __forceinline__ int perm_slot(int j) {
    return (j & ~3) | ((j & 1) << 1) | ((j >> 1) & 1);
}

// ---------------- P = 2^{clamp(...)}: transposed, pair-interleaved quads ----------------
__global__ void __launch_bounds__(256) w1e_kernel(const float* __restrict__ enc,
                                                  const float* __restrict__ W1) {
    extern __shared__ float smem[];
    float* sW1 = smem;               // 128*128
    float* senc = smem + 128 * 128;  // 64 * 129 padded
    int tid = threadIdx.x;
    int b = blockIdx.x >> 3;
    int t0 = (blockIdx.x & 7) * 64;

    for (int i = tid; i < 128 * 128; i += 256) sW1[i] = W1[i];
    for (int i = tid; i < 64 * 128; i += 256) {
        int r = i >> 7, k = i & 127;
        senc[r * 129 + k] = enc[((size_t)b * T + t0 + r) * H + k];
    }
    __syncthreads();

    int t = tid & 63, hg = tid >> 6;
    float acc[32];
#pragma unroll
    for (int i = 0; i < 32; i++) acc[i] = 0.0f;
#pragma unroll 4
    for (int k = 0; k < 128; k++) {
        float e = senc[t * 129 + k];
        const float4* w4 = (const float4*)(sW1 + k * 128 + hg * 32);
#pragma unroll
        for (int q = 0; q < 8; q++) {
            float4 w = w4[q];
            acc[q * 4 + 0] = fmaf(e, w.x, acc[q * 4 + 0]);
            acc[q * 4 + 1] = fmaf(e, w.y, acc[q * 4 + 1]);
            acc[q * 4 + 2] = fmaf(e, w.z, acc[q * 4 + 2]);
            acc[q * 4 + 3] = fmaf(e, w.w, acc[q * 4 + 3]);
        }
    }
    float4* gp = (float4*)g_P;
#pragma unroll
    for (int i4 = 0; i4 < 8; i4++) {
        // pair-interleaved: slots hold h-offsets {0,2,1,3}
        float4 o = make_float4(ex2f(fminf(acc[i4 * 4 + 0] * K2LOG2E, 15.0f)),
                               ex2f(fminf(acc[i4 * 4 + 2] * K2LOG2E, 15.0f)),
                               ex2f(fminf(acc[i4 * 4 + 1] * K2LOG2E, 15.0f)),
                               ex2f(fminf(acc[i4 * 4 + 3] * K2LOG2E, 15.0f)));
        gp[((size_t)b * 32 + hg * 8 + i4) * T + t0 + t] = o;
    }
}

// ---------------- persistent decoder: 2 batches per block, 512 threads ----------------
__global__ void __launch_bounds__(512, 2) decoder_kernel(
    const float* __restrict__ x, const float* __restrict__ h0,
    const float* __restrict__ c0, const float* __restrict__ kern,
    const float* __restrict__ reck, const float* __restrict__ bias,
    const float* __restrict__ W2, const float* __restrict__ V,
    float* __restrict__ out) {
    __shared__ float sh0[H], sh1[H];
    __shared__ float4 sEu0[32], sEu1[32];   // Eu quads (pair-interleaved)
    __shared__ float4 sv4[32];              // -2V quads (pair-interleaved)
    __shared__ float sVs[H];
    __shared__ float4 spart0[512], spart1[512];  // A/C partials (16 KB)
    __shared__ float sact0[G4], sact1[G4];
    __shared__ float sK0[G4], sK1[G4], sb[G4];
    __shared__ float sx0[T * 2], sx1[T * 2];
    __shared__ float sptr0[2], sptr1[2];
    __shared__ float s_sumV;
    __shared__ float rv0[16], rv1[16];
    __shared__ int ri0[16], ri1[16];

    int tid = threadIdx.x;
    int b0 = blockIdx.x * 2, b1 = b0 + 1;
    int lane = tid & 31, wid = tid >> 5;

    for (int i = tid; i < T * 2; i += 512) {
        sx0[i] = x[(size_t)b0 * T * 2 + i];
        sx1[i] = x[(size_t)b1 * T * 2 + i];
    }
    sK0[tid] = kern[tid];
    sK1[tid] = kern[G4 + tid];
    sb[tid] = bias[tid];
    if (tid < H) {
        sh0[tid] = h0[b0 * H + tid];
        sh1[tid] = h0[b1 * H + tid];
        sVs[tid] = V[tid];
    }
    float creg = 0.0f;
    if (tid < 256) creg = c0[(b0 + (tid >> 7)) * H + (tid & 127)];
    if (tid == 0) { sptr0[0] = 1.0f; sptr0[1] = 1.0f; sptr1[0] = 1.0f; sptr1[1] = 1.0f; }
    __syncthreads();
    if (tid < H) ((float*)sv4)[perm_slot(tid)] = -2.0f * sVs[tid];
    if (tid == 0) {
        float sv = 0.0f;
        for (int h = 0; h < H; h++) sv += sVs[h];
        s_sumV = sv;
    }
    __syncthreads();
    float sumV = s_sumV;

    const ulonglong2* wp0 = (const ulonglong2*)((const float4*)g_P + (size_t)b0 * 32 * T + tid);
    const ulonglong2* wp1 = (const ulonglong2*)((const float4*)g_P + (size_t)b1 * 32 * T + tid);
    bool is_g = ((tid >> 7) == 2);  // warp-uniform: g-gate quarter

    for (int s = 0; s < T; s++) {
        // ---- A: partial z for both batches; 32 LDG.128 shared across 2 h-vectors ----
        {
            int p = tid >> 7, q = tid & 127;
            const float4* rk = (const float4*)reck + q;
            float4 a0 = make_float4(0.f, 0.f, 0.f, 0.f);
            float4 a1 = make_float4(0.f, 0.f, 0.f, 0.f);
            int hb = p * 32;
#pragma unroll 8
            for (int h = 0; h < 32; h++) {
                float hv0 = sh0[hb + h];
                float hv1 = sh1[hb + h];
                float4 r4 = __ldg(rk + (size_t)(hb + h) * 128);
                a0.x = fmaf(hv0, r4.x, a0.x); a0.y = fmaf(hv0, r4.y, a0.y);
                a0.z = fmaf(hv0, r4.z, a0.z); a0.w = fmaf(hv0, r4.w, a0.w);
                a1.x = fmaf(hv1, r4.x, a1.x); a1.y = fmaf(hv1, r4.y, a1.y);
                a1.z = fmaf(hv1, r4.z, a1.z); a1.w = fmaf(hv1, r4.w, a1.w);
            }
            spart0[tid] = a0;
            spart1[tid] = a1;
        }
        __syncthreads();

        // ---- B1: z-reduce + activation, gate tid for both batches ----
        {
            const float* sp0 = (const float*)spart0;
            const float* sp1 = (const float*)spart1;
            float z0 = fmaf(sptr0[1], sK1[tid], fmaf(sptr0[0], sK0[tid], sb[tid]))
                     + ((sp0[tid] + sp0[512 + tid]) + (sp0[1024 + tid] + sp0[1536 + tid]));
            float z1 = fmaf(sptr1[1], sK1[tid], fmaf(sptr1[0], sK0[tid], sb[tid]))
                     + ((sp1[tid] + sp1[512 + tid]) + (sp1[1024 + tid] + sp1[1536 + tid]));
            float t0 = tanh_safe(is_g ? z0 : 0.5f * z0);
            sact0[tid] = is_g ? t0 : fmaf(0.5f, t0, 0.5f);
            float t1 = tanh_safe(is_g ? z1 : 0.5f * z1);
            sact1[tid] = is_g ? t1 : fmaf(0.5f, t1, 0.5f);
        }
        __syncthreads();

        // ---- B2: cell update (threads 0..255: batch tid>>7, cell tid&127) ----
        if (tid < 256) {
            int ba = tid >> 7, j = tid & 127;
            const float* sa = ba ? sact1 : sact0;
            float c2 = sa[j + H] * creg + sa[j] * sa[j + 2 * H];
            creg = c2;
            (ba ? sh1 : sh0)[j] = sa[j + 3 * H] * tanh_safe(c2);
        }
        __syncthreads();

        // ---- C: partial u for both batches; 8 LDG.128 shared ----
        {
            int p2 = tid >> 5, g = tid & 31;
            const float4* w2 = (const float4*)W2 + g;
            float4 a0 = make_float4(0.f, 0.f, 0.f, 0.f);
            float4 a1 = make_float4(0.f, 0.f, 0.f, 0.f);
            int hb = p2 * 8;
#pragma unroll
            for (int h = 0; h < 8; h++) {
                float hv0 = sh0[hb + h];
                float hv1 = sh1[hb + h];
                float4 w = __ldg(w2 + (size_t)(hb + h) * 32);
                a0.x = fmaf(hv0, w.x, a0.x); a0.y = fmaf(hv0, w.y, a0.y);
                a0.z = fmaf(hv0, w.z, a0.z); a0.w = fmaf(hv0, w.w, a0.w);
                a1.x = fmaf(hv1, w.x, a1.x); a1.y = fmaf(hv1, w.y, a1.y);
                a1.z = fmaf(hv1, w.z, a1.z); a1.w = fmaf(hv1, w.w, a1.w);
            }
            spart0[tid] = a0;
            spart1[tid] = a1;
        }
        __syncthreads();

        // ---- C-reduce (threads 0..255): Eu per batch ----
        if (tid < 256) {
            int ba = tid >> 7, j = tid & 127;
            const float* sp = ba ? (const float*)spart1 : (const float*)spart0;
            float u = 0.0f;
#pragma unroll
            for (int p2 = 0; p2 < 16; p2++) u += sp[p2 * 128 + j];
            ((float*)(ba ? sEu1 : sEu0))[perm_slot(j)] = ex2f(fminf(u * K2LOG2E, 15.0f));
        }
        __syncthreads();

        // ---- D: score(t'=tid) for both batches, f32x2 4-way combined rcp ----
        float a0a = 0.0f, a1a = 0.0f, a0b = 0.0f, a1b = 0.0f;
#pragma unroll 4
        for (int qd = 0; qd < 32; qd++) {
            ulonglong2 Pq0 = __ldcg(wp0 + (size_t)qd * T);
            ulonglong2 Pq1 = __ldcg(wp1 + (size_t)qd * T);
            ulonglong2 Eq0 = *(const ulonglong2*)&sEu0[qd];
            ulonglong2 Eq1 = *(const ulonglong2*)&sEu1[qd];
            ulonglong2 Vq = *(const ulonglong2*)&sv4[qd];
            // batch 0
            {
                u64 dA = fma2(Pq0.x, Eq0.x, ONE2);
                u64 dB = fma2(Pq0.y, Eq0.y, ONE2);
                u64 prod = mul2(dA, dB);
                u64 nA = mul2(Vq.x, dB);
                u64 n2 = fma2(Vq.y, dA, nA);
                float px, py, n01, n23;
                unpack2(prod, px, py);
                unpack2(n2, n01, n23);
                float num = fmaf(n23, px, n01 * py);
                float r = rcpf(px * py);
                if (qd & 1) a1a = fmaf(num, r, a1a);
                else        a0a = fmaf(num, r, a0a);
            }
            // batch 1
            {
                u64 dA = fma2(Pq1.x, Eq1.x, ONE2);
                u64 dB = fma2(Pq1.y, Eq1.y, ONE2);
                u64 prod = mul2(dA, dB);
                u64 nA = mul2(Vq.x, dB);
                u64 n2 = fma2(Vq.y, dA, nA);
                float px, py, n01, n23;
                unpack2(prod, px, py);
                unpack2(n2, n01, n23);
                float num = fmaf(n23, px, n01 * py);
                float r = rcpf(px * py);
                if (qd & 1) a1b = fmaf(num, r, a1b);
                else        a0b = fmaf(num, r, a0b);
            }
        }
        float score0 = sumV + (a0a + a1a);
        float score1 = sumV + (a0b + a1b);
        __stcs(out + ((size_t)b0 * T + s) * T + tid, score0);
        __stcs(out + ((size_t)b1 * T + s) * T + tid, score1);

        // ---- argmax x2 (tie -> lowest index) ----
        float best0 = score0, best1 = score1;
        int bidx0 = tid, bidx1 = tid;
#pragma unroll
        for (int o = 16; o > 0; o >>= 1) {
            float ov0 = __shfl_xor_sync(0xffffffffu, best0, o);
            int oi0 = __shfl_xor_sync(0xffffffffu, bidx0, o);
            if (ov0 > best0 || (ov0 == best0 && oi0 < bidx0)) { best0 = ov0; bidx0 = oi0; }
            float ov1 = __shfl_xor_sync(0xffffffffu, best1, o);
            int oi1 = __shfl_xor_sync(0xffffffffu, bidx1, o);
            if (ov1 > best1 || (ov1 == best1 && oi1 < bidx1)) { best1 = ov1; bidx1 = oi1; }
        }
        if (lane == 0) {
            rv0[wid] = best0; ri0[wid] = bidx0;
            rv1[wid] = best1; ri1[wid] = bidx1;
        }
        __syncthreads();
        if (wid == 0) {
            float bb = (lane < 16) ? rv0[lane] : rv0[0];
            int bi = (lane < 16) ? ri0[lane] : ri0[0];
#pragma unroll
            for (int o = 8; o > 0; o >>= 1) {
                float ov = __shfl_xor_sync(0xffffffffu, bb, o);
                int oi = __shfl_xor_sync(0xffffffffu, bi, o);
                if (ov > bb || (ov == bb && oi < bi)) { bb = ov; bi = oi; }
            }
            if (lane == 0) { sptr0[0] = sx0[bi * 2]; sptr0[1] = sx0[bi * 2 + 1]; }
        } else if (wid == 1) {
            float bb = (lane < 16) ? rv1[lane] : rv1[0];
            int bi = (lane < 16) ? ri1[lane] : ri1[0];
#pragma unroll
            for (int o = 8; o > 0; o >>= 1) {
                float ov = __shfl_xor_sync(0xffffffffu, bb, o);
                int oi = __shfl_xor_sync(0xffffffffu, bi, o);
                if (ov > bb || (ov == bb && oi < bi)) { bb = ov; bi = oi; }
            }
            if (lane == 0) { sptr1[0] = sx1[bi * 2]; sptr1[1] = sx1[bi * 2 + 1]; }
        }
        __syncthreads();
    }
}

// ---------------- launch: 2 graph nodes ----------------
extern "C" void kernel_launch(void* const* d_in, const int* in_sizes, int n_in,
                              void* d_out, int out_size) {
    const float* x = (const float*)d_in[0];
    const float* enc = (const float*)d_in[1];
    const float* h0 = (const float*)d_in[2];
    const float* c0 = (const float*)d_in[3];
    const float* kern = (const float*)d_in[4];
    const float* reck = (const float*)d_in[5];
    const float* bias = (const float*)d_in[6];
    const float* W1 = (const float*)d_in[7];
    const float* W2 = (const float*)d_in[8];
    const float* V = (const float*)d_in[9];
    float* out = (float*)d_out;

    const int smem_w1e = (128 * 128 + 64 * 129) * 4;  // 98560 B
    cudaFuncSetAttribute(w1e_kernel, cudaFuncAttributeMaxDynamicSharedMemorySize, smem_w1e);
    w1e_kernel<<<B * 8, 256, smem_w1e>>>(enc, W1);
    decoder_kernel<<<B / 2, 512>>>(x, h0, c0, kern, reck, bias, W2, V, out);
}